// round 1
// baseline (speedup 1.0000x reference)
#include <cuda_runtime.h>
#include <cuda_bf16.h>
#include <math.h>

// Problem constants
#define NN 4096
#define DD 2048
#define HH 4
#define HDD 512
#define EE 131072
#define LL 2

// ---------------- scratch (device globals; no allocation) ----------------
__device__ float g_x[NN * DD];      // activations between layers
__device__ float g_q[NN * DD];
__device__ float g_k[NN * DD];
__device__ float g_v[NN * DD];
__device__ float g_agg[NN * DD];
__device__ float g_p[HH * EE];      // scores, then probabilities
__device__ float g_rowmax[HH * NN];
__device__ unsigned int g_bits[NN * NN / 32];  // 2MB uniqueness bitmap
__device__ unsigned char g_uni[EE];
__device__ int g_off[NN + 1];
__device__ int g_cnt[NN];           // degree counts, then scatter cursors
__device__ int g_eid[EE];           // CSR: edge ids grouped by row

// ---------------- graph preprocessing ----------------
__global__ void k_clear_graph() {
    int i = blockIdx.x * blockDim.x + threadIdx.x;
    if (i < NN * NN / 32) g_bits[i] = 0u;
    if (i < NN) g_cnt[i] = 0;
}

__global__ void k_mark(const int* __restrict__ ei) {
    int e = blockIdx.x * blockDim.x + threadIdx.x;
    if (e >= EE) return;
    int r = ei[2 * e], c = ei[2 * e + 1];
    unsigned int bit = (unsigned int)r * NN + (unsigned int)c;
    unsigned int old = atomicOr(&g_bits[bit >> 5], 1u << (bit & 31));
    g_uni[e] = ((old >> (bit & 31)) & 1u) ? 0 : 1;
    atomicAdd(&g_cnt[r], 1);
}

// single-block scan of 4096 degree counts (1024 threads, 4 each)
__global__ void k_scan() {
    __shared__ int sh[1024];
    int t = threadIdx.x;
    int base = t * 4;
    int s0 = g_cnt[base + 0], s1 = g_cnt[base + 1];
    int s2 = g_cnt[base + 2], s3 = g_cnt[base + 3];
    int tot = s0 + s1 + s2 + s3;
    sh[t] = tot;
    __syncthreads();
    for (int off = 1; off < 1024; off <<= 1) {
        int v = (t >= off) ? sh[t - off] : 0;
        __syncthreads();
        sh[t] += v;
        __syncthreads();
    }
    int excl = sh[t] - tot;
    g_off[base + 0] = excl;
    g_off[base + 1] = excl + s0;
    g_off[base + 2] = excl + s0 + s1;
    g_off[base + 3] = excl + s0 + s1 + s2;
    if (t == 1023) g_off[NN] = sh[1023];
    // reset cursors for scatter
    g_cnt[base + 0] = 0; g_cnt[base + 1] = 0;
    g_cnt[base + 2] = 0; g_cnt[base + 3] = 0;
}

__global__ void k_scatter(const int* __restrict__ ei) {
    int e = blockIdx.x * blockDim.x + threadIdx.x;
    if (e >= EE) return;
    int r = ei[2 * e];
    int pos = g_off[r] + atomicAdd(&g_cnt[r], 1);
    g_eid[pos] = e;
}

// ---------------- SGEMM: C[M,Nc] = A[M,K] @ B[K,Nc] + bias[Nc] ----------------
#define BM 128
#define BN 128
#define BK 16
#define TM 8
#define TN 8

__global__ __launch_bounds__(256) void k_sgemm(
    const float* __restrict__ A, const float* __restrict__ B,
    const float* __restrict__ bias, float* __restrict__ C,
    int M, int K, int Nc)
{
    __shared__ float As[BK][BM];
    __shared__ float Bs[BK][BN];

    int bx = blockIdx.x;   // N tile
    int by = blockIdx.y;   // M tile
    int tid = threadIdx.x;
    int tr = tid / 16;     // 0..15
    int tc = tid % 16;     // 0..15

    int arow = tid / 4;        // 0..63
    int acol = (tid % 4) * 4;  // 0,4,8,12
    int brow = tid / 32;       // 0..7
    int bcol = (tid % 32) * 4; // 0..124

    const float* Ab = A + (size_t)(by * BM) * K;
    const float* Bb = B + bx * BN;

    float acc[TM][TN];
#pragma unroll
    for (int i = 0; i < TM; i++)
#pragma unroll
        for (int j = 0; j < TN; j++) acc[i][j] = 0.0f;

    for (int k0 = 0; k0 < K; k0 += BK) {
#pragma unroll
        for (int i = 0; i < 2; i++) {
            int r = arow + i * 64;
            float4 va = *(const float4*)(Ab + (size_t)r * K + k0 + acol);
            As[acol + 0][r] = va.x;
            As[acol + 1][r] = va.y;
            As[acol + 2][r] = va.z;
            As[acol + 3][r] = va.w;
        }
#pragma unroll
        for (int i = 0; i < 2; i++) {
            int r = brow + i * 8;
            float4 vb = *(const float4*)(Bb + (size_t)(k0 + r) * Nc + bcol);
            *(float4*)&Bs[r][bcol] = vb;
        }
        __syncthreads();

#pragma unroll
        for (int kk = 0; kk < BK; kk++) {
            float ra[TM], rb[TN];
            *(float4*)&ra[0] = *(const float4*)&As[kk][tr * TM];
            *(float4*)&ra[4] = *(const float4*)&As[kk][tr * TM + 4];
            *(float4*)&rb[0] = *(const float4*)&Bs[kk][tc * TN];
            *(float4*)&rb[4] = *(const float4*)&Bs[kk][tc * TN + 4];
#pragma unroll
            for (int i = 0; i < TM; i++)
#pragma unroll
                for (int j = 0; j < TN; j++)
                    acc[i][j] += ra[i] * rb[j];
        }
        __syncthreads();
    }

#pragma unroll
    for (int i = 0; i < TM; i++) {
        int row = by * BM + tr * TM + i;
        float* Crow = C + (size_t)row * Nc + bx * BN + tc * TN;
        const float* brow_p = bias + bx * BN + tc * TN;
#pragma unroll
        for (int j = 0; j < TN; j += 4) {
            float4 o;
            o.x = acc[i][j + 0] + brow_p[j + 0];
            o.y = acc[i][j + 1] + brow_p[j + 1];
            o.z = acc[i][j + 2] + brow_p[j + 2];
            o.w = acc[i][j + 3] + brow_p[j + 3];
            *(float4*)(Crow + j) = o;
        }
    }
}

// ---------------- attention ----------------
__global__ void k_clear_attn() {
    int i = blockIdx.x * blockDim.x + threadIdx.x;
    if (i < HH * NN) g_rowmax[i] = -3.0e38f;
}

// one warp per edge: 4 head dot-products of length 512
__global__ void k_scores(const int* __restrict__ ei,
                         const float* __restrict__ q,
                         const float* __restrict__ k)
{
    int warp = (blockIdx.x * blockDim.x + threadIdx.x) >> 5;
    int lane = threadIdx.x & 31;
    if (warp >= EE) return;
    int r = ei[2 * warp], c = ei[2 * warp + 1];
    const float4* qr = (const float4*)(q + (size_t)r * DD);
    const float4* kr = (const float4*)(k + (size_t)c * DD);
    const float scale = 0.044194173824159216f;  // 1/sqrt(512)
#pragma unroll
    for (int h = 0; h < HH; h++) {
        float acc = 0.0f;
#pragma unroll
        for (int i = 0; i < 4; i++) {
            int idx = h * 128 + i * 32 + lane;
            float4 a = qr[idx];
            float4 b = kr[idx];
            acc += a.x * b.x + a.y * b.y + a.z * b.z + a.w * b.w;
        }
#pragma unroll
        for (int o = 16; o; o >>= 1)
            acc += __shfl_xor_sync(0xffffffffu, acc, o);
        if (lane == 0) g_p[h * EE + warp] = acc * scale;
    }
}

__device__ __forceinline__ void atomicMaxF(float* addr, float v) {
    int old = __float_as_int(*addr);
    while (__int_as_float(old) < v) {
        int assumed = old;
        old = atomicCAS((int*)addr, assumed, __float_as_int(v));
        if (old == assumed) break;
    }
}

__global__ void k_rowmax(const int* __restrict__ ei) {
    int idx = blockIdx.x * blockDim.x + threadIdx.x;
    if (idx >= HH * EE) return;
    int h = idx >> 17;          // EE = 2^17
    int e = idx & (EE - 1);
    int r = ei[2 * e];
    atomicMaxF(&g_rowmax[h * NN + r], g_p[idx]);
}

__global__ void k_pexp(const int* __restrict__ ei) {
    int idx = blockIdx.x * blockDim.x + threadIdx.x;
    if (idx >= HH * EE) return;
    int h = idx >> 17;
    int e = idx & (EE - 1);
    int r = ei[2 * e];
    g_p[idx] = expf(g_p[idx] - g_rowmax[h * NN + r]);
}

// one block (256 threads) per destination row; each thread owns 8 output dims
__global__ __launch_bounds__(256) void k_aggregate(
    const int* __restrict__ ei, const float* __restrict__ v,
    float* __restrict__ agg)
{
    int r = blockIdx.x;
    int start = g_off[r], end = g_off[r + 1];
    __shared__ float sinv[HH];
    int t = threadIdx.x;

    if (t < HH) {
        // softmax denominator over UNIQUE edges only (matches reference mask dedup)
        float d = 0.0f;
        for (int j = start; j < end; j++) {
            int e = g_eid[j];
            if (g_uni[e]) d += g_p[t * EE + e];
        }
        sinv[t] = (d > 0.0f) ? (1.0f / d) : 0.0f;
    }
    __syncthreads();

    int d0 = t * 8;
    int h = d0 >> 9;       // HDD = 512
    float inv = sinv[h];

    float acc[8];
#pragma unroll
    for (int i = 0; i < 8; i++) acc[i] = 0.0f;

    for (int j = start; j < end; j++) {
        int e = g_eid[j];
        int c = ei[2 * e + 1];
        float w = g_p[h * EE + e] * inv;
        const float4* vr = (const float4*)(v + (size_t)c * DD + d0);
        float4 a = vr[0], b = vr[1];
        acc[0] += w * a.x; acc[1] += w * a.y;
        acc[2] += w * a.z; acc[3] += w * a.w;
        acc[4] += w * b.x; acc[5] += w * b.y;
        acc[6] += w * b.z; acc[7] += w * b.w;
    }

    float4* o = (float4*)(agg + (size_t)r * DD + d0);
    o[0] = make_float4(acc[0], acc[1], acc[2], acc[3]);
    o[1] = make_float4(acc[4], acc[5], acc[6], acc[7]);
}

// ---------------- host launch ----------------
extern "C" void kernel_launch(void* const* d_in, const int* in_sizes, int n_in,
                              void* d_out, int out_size) {
    const float* feats = (const float*)d_in[0];
    const float* Wq = (const float*)d_in[1];
    const float* bq = (const float*)d_in[2];
    const float* Wk = (const float*)d_in[3];
    const float* bk = (const float*)d_in[4];
    const float* Wv = (const float*)d_in[5];
    const float* bv = (const float*)d_in[6];
    const float* Wo = (const float*)d_in[7];
    const float* bo = (const float*)d_in[8];
    const int* ei = (const int*)d_in[9];

    float *px, *pq, *pk, *pv, *pagg;
    cudaGetSymbolAddress((void**)&px, g_x);
    cudaGetSymbolAddress((void**)&pq, g_q);
    cudaGetSymbolAddress((void**)&pk, g_k);
    cudaGetSymbolAddress((void**)&pv, g_v);
    cudaGetSymbolAddress((void**)&pagg, g_agg);

    // graph preprocessing (layer-independent)
    k_clear_graph<<<(NN * NN / 32 + 255) / 256, 256>>>();
    k_mark<<<EE / 256, 256>>>(ei);
    k_scan<<<1, 1024>>>();
    k_scatter<<<EE / 256, 256>>>(ei);

    dim3 ggrid(DD / BN, NN / BM);  // (16, 32)

    for (int l = 0; l < LL; l++) {
        const float* X = (l == 0) ? feats : px;
        size_t wo = (size_t)l * DD * DD;
        size_t bofs = (size_t)l * DD;

        k_sgemm<<<ggrid, 256>>>(X, Wq + wo, bq + bofs, pq, NN, DD, DD);
        k_sgemm<<<ggrid, 256>>>(X, Wk + wo, bk + bofs, pk, NN, DD, DD);
        k_sgemm<<<ggrid, 256>>>(X, Wv + wo, bv + bofs, pv, NN, DD, DD);

        k_clear_attn<<<(HH * NN + 255) / 256, 256>>>();
        k_scores<<<EE * 32 / 256, 256>>>(ei, pq, pk);
        k_rowmax<<<HH * EE / 256, 256>>>(ei);
        k_pexp<<<HH * EE / 256, 256>>>(ei);
        k_aggregate<<<NN, 256>>>(ei, pv, pagg);

        float* Cout = (l == 0) ? px : (float*)d_out;
        k_sgemm<<<ggrid, 256>>>(pagg, Wo + wo, bo + bofs, Cout, NN, DD, DD);
    }
}

// round 4
// speedup vs baseline: 2.6208x; 2.6208x over previous
#include <cuda_runtime.h>
#include <cuda_bf16.h>
#include <math.h>

// Problem constants
#define NN 4096
#define DD 2048
#define HH 4
#define HDD 512
#define EE 131072
#define LL 2

// ---------------- scratch (device globals; no allocation) ----------------
__device__ float g_x[NN * DD];      // activations between layers
__device__ float g_q[NN * DD];
__device__ float g_k[NN * DD];
__device__ float g_v[NN * DD];
__device__ float g_agg[NN * DD];
__device__ float g_p[HH * EE];      // scores, then probabilities
__device__ float g_rowmax[HH * NN];
__device__ unsigned int g_bits[NN * NN / 32];  // 2MB uniqueness bitmap
__device__ unsigned char g_uni[EE];
__device__ int g_off[NN + 1];
__device__ int g_cnt[NN];           // degree counts, then scatter cursors
__device__ int g_eid[EE];           // CSR: edge ids grouped by row

// ---------------- graph preprocessing ----------------
__global__ void k_clear_graph() {
    int i = blockIdx.x * blockDim.x + threadIdx.x;
    if (i < NN * NN / 32) g_bits[i] = 0u;
    if (i < NN) g_cnt[i] = 0;
}

__global__ void k_mark(const int* __restrict__ ei) {
    int e = blockIdx.x * blockDim.x + threadIdx.x;
    if (e >= EE) return;
    int r = ei[2 * e], c = ei[2 * e + 1];
    unsigned int bit = (unsigned int)r * NN + (unsigned int)c;
    unsigned int old = atomicOr(&g_bits[bit >> 5], 1u << (bit & 31));
    g_uni[e] = ((old >> (bit & 31)) & 1u) ? 0 : 1;
    atomicAdd(&g_cnt[r], 1);
}

// single-block scan of 4096 degree counts (1024 threads, 4 each)
__global__ void k_scan() {
    __shared__ int sh[1024];
    int t = threadIdx.x;
    int base = t * 4;
    int s0 = g_cnt[base + 0], s1 = g_cnt[base + 1];
    int s2 = g_cnt[base + 2], s3 = g_cnt[base + 3];
    int tot = s0 + s1 + s2 + s3;
    sh[t] = tot;
    __syncthreads();
    for (int off = 1; off < 1024; off <<= 1) {
        int v = (t >= off) ? sh[t - off] : 0;
        __syncthreads();
        sh[t] += v;
        __syncthreads();
    }
    int excl = sh[t] - tot;
    g_off[base + 0] = excl;
    g_off[base + 1] = excl + s0;
    g_off[base + 2] = excl + s0 + s1;
    g_off[base + 3] = excl + s0 + s1 + s2;
    if (t == 1023) g_off[NN] = sh[1023];
    g_cnt[base + 0] = 0; g_cnt[base + 1] = 0;
    g_cnt[base + 2] = 0; g_cnt[base + 3] = 0;
}

__global__ void k_scatter(const int* __restrict__ ei) {
    int e = blockIdx.x * blockDim.x + threadIdx.x;
    if (e >= EE) return;
    int r = ei[2 * e];
    int pos = g_off[r] + atomicAdd(&g_cnt[r], 1);
    g_eid[pos] = e;
}

// ---------------- TF32 tensor-core GEMM ----------------
// C[M,N] = A[M,K] @ B[K,N] + bias[N]
// Tile: 128x128x32, 8 warps (4m x 2n), warp tile 32x64 via m16n8k8.
// smem strides chosen so all fragment LDS are bank-conflict-free:
//   As[m][k] stride 36 floats; Bs[k][n] stride 136 floats.

#define GBM 128
#define GBN 128
#define GBK 32
#define A_STRIDE 36
#define B_STRIDE 136
#define A_TILE_F (GBM * A_STRIDE)   // 4608 floats
#define B_TILE_F (GBK * B_STRIDE)   // 4352 floats
#define STAGE_F  (A_TILE_F + B_TILE_F)
#define SMEM_BYTES (2 * STAGE_F * 4)  // 71680

__device__ __forceinline__ unsigned int f2tf32(float f) {
    unsigned int u;
    asm("cvt.rna.tf32.f32 %0, %1;" : "=r"(u) : "f"(f));
    return u;
}

__device__ __forceinline__ void cp16(void* s, const void* g) {
    unsigned long long sp = __cvta_generic_to_shared(s);
    asm volatile("cp.async.cg.shared.global [%0], [%1], 16;"
                 :: "l"(sp), "l"(g));
}

__device__ __forceinline__ void load_tile(
    const float* __restrict__ A, const float* __restrict__ B,
    float* As, float* Bs, int tileM, int tileN, int k0, int K, int N, int tid)
{
#pragma unroll
    for (int i = 0; i < 4; i++) {           // A: 128 rows x 32 floats = 1024 chunks
        int c = tid + 256 * i;
        int row = c >> 3;
        int col = (c & 7) * 4;
        cp16(As + row * A_STRIDE + col,
             A + (size_t)(tileM + row) * K + k0 + col);
    }
#pragma unroll
    for (int i = 0; i < 4; i++) {           // B: 32 rows x 128 floats = 1024 chunks
        int c = tid + 256 * i;
        int row = c >> 5;
        int col = (c & 31) * 4;
        cp16(Bs + row * B_STRIDE + col,
             B + (size_t)(k0 + row) * N + tileN + col);
    }
    asm volatile("cp.async.commit_group;");
}

__global__ __launch_bounds__(256, 2) void k_tf32gemm(
    const float* __restrict__ A, const float* __restrict__ B,
    const float* __restrict__ bias, float* __restrict__ C,
    int M, int K, int N)
{
    extern __shared__ float smem[];
    float* As[2] = { smem, smem + STAGE_F };
    float* Bs[2] = { smem + A_TILE_F, smem + STAGE_F + A_TILE_F };

    int tid = threadIdx.x;
    int wid = tid >> 5;
    int lane = tid & 31;
    int gid = lane >> 2;   // group id 0..7
    int tig = lane & 3;    // thread-in-group 0..3

    int warp_m = wid >> 1;          // 0..3 -> 32 rows each
    int warp_n = wid & 1;           // 0..1 -> 64 cols each
    int tileM = blockIdx.y * GBM;
    int tileN = blockIdx.x * GBN;

    float acc[2][8][4];
#pragma unroll
    for (int mt = 0; mt < 2; mt++)
#pragma unroll
        for (int nt = 0; nt < 8; nt++)
#pragma unroll
            for (int r = 0; r < 4; r++) acc[mt][nt][r] = 0.0f;

    int nk = K / GBK;
    load_tile(A, B, As[0], Bs[0], tileM, tileN, 0, K, N, tid);

    for (int kt = 0; kt < nk; kt++) {
        if (kt + 1 < nk)
            load_tile(A, B, As[(kt + 1) & 1], Bs[(kt + 1) & 1],
                      tileM, tileN, (kt + 1) * GBK, K, N, tid);
        if (kt + 1 < nk)
            asm volatile("cp.async.wait_group 1;");
        else
            asm volatile("cp.async.wait_group 0;");
        __syncthreads();

        const float* Ab = As[kt & 1];
        const float* Bb = Bs[kt & 1];

#pragma unroll
        for (int ks = 0; ks < 4; ks++) {
            int kb = ks * 8;
            unsigned int af[2][4];
#pragma unroll
            for (int mt = 0; mt < 2; mt++) {
                int m0 = warp_m * 32 + mt * 16 + gid;
                af[mt][0] = f2tf32(Ab[m0 * A_STRIDE + kb + tig]);
                af[mt][1] = f2tf32(Ab[(m0 + 8) * A_STRIDE + kb + tig]);
                af[mt][2] = f2tf32(Ab[m0 * A_STRIDE + kb + tig + 4]);
                af[mt][3] = f2tf32(Ab[(m0 + 8) * A_STRIDE + kb + tig + 4]);
            }
            unsigned int bf[8][2];
#pragma unroll
            for (int nt = 0; nt < 8; nt++) {
                int n0 = warp_n * 64 + nt * 8 + gid;
                bf[nt][0] = f2tf32(Bb[(kb + tig) * B_STRIDE + n0]);
                bf[nt][1] = f2tf32(Bb[(kb + tig + 4) * B_STRIDE + n0]);
            }
#pragma unroll
            for (int mt = 0; mt < 2; mt++)
#pragma unroll
                for (int nt = 0; nt < 8; nt++) {
                    asm volatile(
                        "mma.sync.aligned.m16n8k8.row.col.f32.tf32.tf32.f32 "
                        "{%0,%1,%2,%3}, {%4,%5,%6,%7}, {%8,%9}, {%0,%1,%2,%3};"
                        : "+f"(acc[mt][nt][0]), "+f"(acc[mt][nt][1]),
                          "+f"(acc[mt][nt][2]), "+f"(acc[mt][nt][3])
                        : "r"(af[mt][0]), "r"(af[mt][1]),
                          "r"(af[mt][2]), "r"(af[mt][3]),
                          "r"(bf[nt][0]), "r"(bf[nt][1]));
                }
        }
        __syncthreads();
    }

    // epilogue: c0,c1 -> (row, col..col+1); c2,c3 -> (row+8, ...)
#pragma unroll
    for (int mt = 0; mt < 2; mt++) {
#pragma unroll
        for (int nt = 0; nt < 8; nt++) {
            int row = tileM + warp_m * 32 + mt * 16 + gid;
            int col = tileN + warp_n * 64 + nt * 8 + tig * 2;
            float b0 = bias[col], b1 = bias[col + 1];
            float2 o0 = make_float2(acc[mt][nt][0] + b0, acc[mt][nt][1] + b1);
            float2 o1 = make_float2(acc[mt][nt][2] + b0, acc[mt][nt][3] + b1);
            *(float2*)(C + (size_t)row * N + col) = o0;
            *(float2*)(C + (size_t)(row + 8) * N + col) = o1;
        }
    }
}

// ---------------- attention ----------------
__global__ void k_clear_attn() {
    int i = blockIdx.x * blockDim.x + threadIdx.x;
    if (i < HH * NN) g_rowmax[i] = -3.0e38f;
}

// one warp per edge: 4 head dot-products of length 512
__global__ void k_scores(const int* __restrict__ ei,
                         const float* __restrict__ q,
                         const float* __restrict__ k)
{
    int warp = (blockIdx.x * blockDim.x + threadIdx.x) >> 5;
    int lane = threadIdx.x & 31;
    if (warp >= EE) return;
    int r = ei[2 * warp], c = ei[2 * warp + 1];
    const float4* qr = (const float4*)(q + (size_t)r * DD);
    const float4* kr = (const float4*)(k + (size_t)c * DD);
    const float scale = 0.044194173824159216f;  // 1/sqrt(512)
#pragma unroll
    for (int h = 0; h < HH; h++) {
        float acc = 0.0f;
#pragma unroll
        for (int i = 0; i < 4; i++) {
            int idx = h * 128 + i * 32 + lane;
            float4 a = qr[idx];
            float4 b = kr[idx];
            acc += a.x * b.x + a.y * b.y + a.z * b.z + a.w * b.w;
        }
#pragma unroll
        for (int o = 16; o; o >>= 1)
            acc += __shfl_xor_sync(0xffffffffu, acc, o);
        if (lane == 0) g_p[h * EE + warp] = acc * scale;
    }
}

__device__ __forceinline__ void atomicMaxF(float* addr, float v) {
    int old = __float_as_int(*addr);
    while (__int_as_float(old) < v) {
        int assumed = old;
        old = atomicCAS((int*)addr, assumed, __float_as_int(v));
        if (old == assumed) break;
    }
}

__global__ void k_rowmax(const int* __restrict__ ei) {
    int idx = blockIdx.x * blockDim.x + threadIdx.x;
    if (idx >= HH * EE) return;
    int h = idx >> 17;          // EE = 2^17
    int e = idx & (EE - 1);
    int r = ei[2 * e];
    atomicMaxF(&g_rowmax[h * NN + r], g_p[idx]);
}

__global__ void k_pexp(const int* __restrict__ ei) {
    int idx = blockIdx.x * blockDim.x + threadIdx.x;
    if (idx >= HH * EE) return;
    int h = idx >> 17;
    int e = idx & (EE - 1);
    int r = ei[2 * e];
    g_p[idx] = expf(g_p[idx] - g_rowmax[h * NN + r]);
}

// one block (256 threads) per destination row; each thread owns 8 output dims
__global__ __launch_bounds__(256) void k_aggregate(
    const int* __restrict__ ei, const float* __restrict__ v,
    float* __restrict__ agg)
{
    int r = blockIdx.x;
    int start = g_off[r], end = g_off[r + 1];
    __shared__ float sinv[HH];
    int t = threadIdx.x;

    if (t < HH) {
        // softmax denominator over UNIQUE edges only (matches reference mask dedup)
        float d = 0.0f;
        for (int j = start; j < end; j++) {
            int e = g_eid[j];
            if (g_uni[e]) d += g_p[t * EE + e];
        }
        sinv[t] = (d > 0.0f) ? (1.0f / d) : 0.0f;
    }
    __syncthreads();

    int d0 = t * 8;
    int h = d0 >> 9;       // HDD = 512
    float inv = sinv[h];

    float acc[8];
#pragma unroll
    for (int i = 0; i < 8; i++) acc[i] = 0.0f;

    for (int j = start; j < end; j++) {
        int e = g_eid[j];
        int c = ei[2 * e + 1];
        float w = g_p[h * EE + e] * inv;
        const float4* vr = (const float4*)(v + (size_t)c * DD + d0);
        float4 a = vr[0], b = vr[1];
        acc[0] += w * a.x; acc[1] += w * a.y;
        acc[2] += w * a.z; acc[3] += w * a.w;
        acc[4] += w * b.x; acc[5] += w * b.y;
        acc[6] += w * b.z; acc[7] += w * b.w;
    }

    float4* o = (float4*)(agg + (size_t)r * DD + d0);
    o[0] = make_float4(acc[0], acc[1], acc[2], acc[3]);
    o[1] = make_float4(acc[4], acc[5], acc[6], acc[7]);
}

// ---------------- host launch ----------------
extern "C" void kernel_launch(void* const* d_in, const int* in_sizes, int n_in,
                              void* d_out, int out_size) {
    const float* feats = (const float*)d_in[0];
    const float* Wq = (const float*)d_in[1];
    const float* bq = (const float*)d_in[2];
    const float* Wk = (const float*)d_in[3];
    const float* bk = (const float*)d_in[4];
    const float* Wv = (const float*)d_in[5];
    const float* bv = (const float*)d_in[6];
    const float* Wo = (const float*)d_in[7];
    const float* bo = (const float*)d_in[8];
    const int* ei = (const int*)d_in[9];

    float *px, *pq, *pk, *pv, *pagg;
    cudaGetSymbolAddress((void**)&px, g_x);
    cudaGetSymbolAddress((void**)&pq, g_q);
    cudaGetSymbolAddress((void**)&pk, g_k);
    cudaGetSymbolAddress((void**)&pv, g_v);
    cudaGetSymbolAddress((void**)&pagg, g_agg);

    cudaFuncSetAttribute(k_tf32gemm,
                         cudaFuncAttributeMaxDynamicSharedMemorySize, SMEM_BYTES);

    // graph preprocessing (layer-independent)
    k_clear_graph<<<(NN * NN / 32 + 255) / 256, 256>>>();
    k_mark<<<EE / 256, 256>>>(ei);
    k_scan<<<1, 1024>>>();
    k_scatter<<<EE / 256, 256>>>(ei);

    dim3 ggrid(DD / GBN, NN / GBM);  // (16, 32)

    for (int l = 0; l < LL; l++) {
        const float* X = (l == 0) ? feats : px;
        size_t wo = (size_t)l * DD * DD;
        size_t bofs = (size_t)l * DD;

        k_tf32gemm<<<ggrid, 256, SMEM_BYTES>>>(X, Wq + wo, bq + bofs, pq, NN, DD, DD);
        k_tf32gemm<<<ggrid, 256, SMEM_BYTES>>>(X, Wk + wo, bk + bofs, pk, NN, DD, DD);
        k_tf32gemm<<<ggrid, 256, SMEM_BYTES>>>(X, Wv + wo, bv + bofs, pv, NN, DD, DD);

        k_clear_attn<<<(HH * NN + 255) / 256, 256>>>();
        k_scores<<<EE * 32 / 256, 256>>>(ei, pq, pk);
        k_rowmax<<<HH * EE / 256, 256>>>(ei);
        k_pexp<<<HH * EE / 256, 256>>>(ei);
        k_aggregate<<<NN, 256>>>(ei, pv, pagg);

        float* Cout = (l == 0) ? px : (float*)d_out;
        k_tf32gemm<<<ggrid, 256, SMEM_BYTES>>>(pagg, Wo + wo, bo + bofs, Cout, NN, DD, DD);
    }
}